// round 6
// baseline (speedup 1.0000x reference)
#include <cuda_runtime.h>
#include <cuda_bf16.h>

// Fixed-shape problem: N=2000 nodes, F=2, HIDDEN=64, K=3, G=256 graphs, E~7998 edges
#define NN    2000
#define EMAXS 8192          // smem edge capacity (actual E ~7998)
#define HID   64
#define TPB   1024

typedef unsigned long long ull;

// ---------------- f32x2 packed-math helpers ----------------
__device__ __forceinline__ ull pk2(float lo, float hi) {
    ull r; asm("mov.b64 %0,{%1,%2};" : "=l"(r) : "f"(lo), "f"(hi)); return r;
}
__device__ __forceinline__ void upk2(ull v, float& lo, float& hi) {
    asm("mov.b64 {%0,%1}, %2;" : "=f"(lo), "=f"(hi) : "l"(v));
}
__device__ __forceinline__ ull fma2v(ull a, ull b, ull c) {
    ull d; asm("fma.rn.f32x2 %0, %1, %2, %3;" : "=l"(d) : "l"(a), "l"(b), "l"(c)); return d;
}

// ---------------- device-global scratch ----------------
__device__ int  g_ptr[NN + 1];
__device__ int  g_perm[NN];
__device__ int2 g_edge[EMAXS];   // .x = src slot, .y = bits of gcn_norm weight

// ---------------- fused prepass: smem atomics + degree counting-sort ----------------
__global__ __launch_bounds__(1024)
void k_pre(const int* __restrict__ row, const int* __restrict__ col,
           const float* __restrict__ ew, int E) {
    __shared__ float sdeg[NN];
    __shared__ int   scnt[NN];
    __shared__ int   sinv[NN];
    __shared__ int   scur[NN];
    __shared__ int   hist[64];
    __shared__ int   hoff[64];
    __shared__ int   warpsum[32];
    const int t = threadIdx.x;

    for (int i = t; i < NN; i += 1024) { sdeg[i] = 0.f; scnt[i] = 0; }
    if (t < 64) hist[t] = 0;
    __syncthreads();

    for (int e = t; e < E; e += 1024) {
        int c = col[e];
        atomicAdd(&sdeg[c], ew[e]);
        atomicAdd(&scnt[c], 1);
    }
    __syncthreads();

    for (int n = t; n < NN; n += 1024) {
        int d = scnt[n]; if (d > 63) d = 63;
        atomicAdd(&hist[d], 1);
    }
    __syncthreads();
    if (t == 0) {
        int run = 0;
        for (int d = 0; d < 64; d++) { hoff[d] = run; run += hist[d]; }
    }
    __syncthreads();

    for (int n = t; n < NN; n += 1024) {
        int d = scnt[n]; int dc = (d > 63) ? 63 : d;
        int slot = atomicAdd(&hoff[dc], 1);
        sinv[n] = slot;
        g_perm[slot] = n;
        scur[slot] = d;
    }
    __syncthreads();

    {   // exclusive scan of slot-degrees -> g_ptr / cursors
        int i0 = 2 * t, i1 = 2 * t + 1;
        int a0 = (i0 < NN) ? scur[i0] : 0;
        int a1 = (i1 < NN) ? scur[i1] : 0;
        int tot = a0 + a1;
        int lane = t & 31, wid = t >> 5;
        int v = tot;
        #pragma unroll
        for (int o = 1; o < 32; o <<= 1) {
            int u = __shfl_up_sync(0xFFFFFFFFu, v, o);
            if (lane >= o) v += u;
        }
        if (lane == 31) warpsum[wid] = v;
        __syncthreads();
        if (wid == 0) {
            int w = warpsum[lane];
            #pragma unroll
            for (int o = 1; o < 32; o <<= 1) {
                int u = __shfl_up_sync(0xFFFFFFFFu, w, o);
                if (lane >= o) w += u;
            }
            warpsum[lane] = w;
        }
        __syncthreads();
        int base = v - tot + (wid ? warpsum[wid - 1] : 0);
        if (i0 < NN) { scur[i0] = base;      g_ptr[i0] = base; }
        if (i1 < NN) { scur[i1] = base + a0; g_ptr[i1] = base + a0; }
        if (t == 0)  g_ptr[NN] = E;
    }
    __syncthreads();

    for (int e = t; e < E; e += 1024) {
        int r = row[e], c = col[e];
        float dr = sdeg[r], dc = sdeg[c];
        float ir = (dr > 0.f) ? rsqrtf(dr) : 0.f;
        float ic = (dc > 0.f) ? rsqrtf(dc) : 0.f;
        float nrm = ir * ew[e] * ic;
        int p = atomicAdd(&scur[sinv[c]], 1);
        g_edge[p] = make_int2(sinv[r], __float_as_int(nrm));
    }
}

// ---------------- main fused kernel: one CTA per TWO graphs ----------------
// Node buffers: ulonglong2 per node = ( pk2(feat0_A, feat0_B), pk2(feat1_A, feat1_B) )
// i.e. the f32x2 lanes hold the TWO GRAPHS for one feature.
// smem: 4 node buffers + edge CSR + duplicated weights + sptr
#define SMEM_BYTES (4 * NN * 16 + EMAXS * 8 + 4096 + 4096 + 512 + (NN + 1) * 4)

__global__ __launch_bounds__(TPB, 1)
void k_main(const float* __restrict__ x,
            const float* __restrict__ W1, const float* __restrict__ b1,
            const float* __restrict__ W2, const float* __restrict__ b2,
            float* __restrict__ out, int G, int E) {
    extern __shared__ float sm[];
    ulonglong2* pb0 = (ulonglong2*)sm;
    ulonglong2* pb1 = pb0 + NN;
    ulonglong2* pb2 = pb1 + NN;
    ulonglong2* pb3 = pb2 + NN;
    int2* se  = (int2*)(pb3 + NN);         // staged edges
    ull*  w1d = (ull*)(se + EMAXS);        // [64 j][8 i]  pk2(W1cat[i][j], dup)
    ull*  w2d = w1d + 512;                 // [64 j][8 c]  pk2(W2cat[j][c], dup)
    ull*  b1d = w2d + 512;                 // [64] pk2(b1[j], dup)
    int*  sptr = (int*)(b1d + 64);

    const int t  = threadIdx.x;
    const int bs = blockDim.x;
    const int gA = 2 * blockIdx.x;
    int gB = gA + 1; bool hasB = (gB < G); if (!hasB) gB = gA;

    // stage duplicated weights
    for (int i = t; i < 512; i += bs) {
        int j = i >> 3, c = i & 7;
        float a = W1[c * HID + j];                         // W1cat[c][j], c = hop*2+feat
        w1d[i] = pk2(a, a);
        float v = W2[(c >> 1) * (HID * 2) + j * 2 + (c & 1)];  // W2cat[j][c]
        w2d[i] = pk2(v, v);
    }
    for (int i = t; i < HID; i += bs) { float v = b1[i]; b1d[i] = pk2(v, v); }
    for (int i = t; i < NN + 1; i += bs) sptr[i] = g_ptr[i];
    for (int i = t; i < E; i += bs) se[i] = g_edge[i];

    // stage x into slot space with {A,B}-in-lanes transpose -> pb0
    const ull* xgA = (const ull*)(x + (size_t)gA * 2 * NN);
    const ull* xgB = (const ull*)(x + (size_t)gB * 2 * NN);
    for (int s = t; s < NN; s += bs) {
        int node = __ldg(&g_perm[s]);
        float a0, a1, c0, c1;
        upk2(__ldg(&xgA[node]), a0, a1);
        upk2(__ldg(&xgB[node]), c0, c1);
        pb0[s] = make_ulonglong2(pk2(a0, c0), pk2(a1, c1));
    }
    __syncthreads();

    // ---- single-slot gather (R4 structure, smem edges) ----
    #define GATHER(PIN, POUT, ADD, USE_ADD)                                    \
    for (int n = t; n < NN; n += bs) {                                         \
        int b = sptr[n], e = sptr[n + 1];                                      \
        ull a0 = 0, a1 = 0;                                                    \
        if (USE_ADD) { ulonglong2 z = ADD[n]; a0 = z.x; a1 = z.y; }            \
        for (int q = b; q < e; q++) {                                          \
            int2 ed = se[q];                                                   \
            float w = __int_as_float(ed.y);                                    \
            ull ww = pk2(w, w);                                                \
            ulonglong2 v = PIN[ed.x];                                          \
            a0 = fma2v(v.x, ww, a0); a1 = fma2v(v.y, ww, a1);                  \
        }                                                                      \
        POUT[n] = make_ulonglong2(a0, a1);                                     \
    }

    // layer-1 hops
    GATHER(pb0, pb1, pb0, false); __syncthreads();
    GATHER(pb1, pb2, pb0, false); __syncthreads();
    GATHER(pb2, pb3, pb0, false); __syncthreads();

    // ---- dense sandwich: [8] -> 64 (relu) -> [8], both graphs per pass, no spills ----
    {
        const ulonglong2* w1v = (const ulonglong2*)w1d;   // 4 per j
        const ulonglong2* w2v = (const ulonglong2*)w2d;   // 4 per j
        #pragma unroll 1
        for (int n = t; n < NN; n += bs) {
            ulonglong2 q0 = pb0[n], q1 = pb1[n], q2 = pb2[n], q3 = pb3[n];
            ull p0 = q0.x, p1 = q0.y, p2 = q1.x, p3 = q1.y;
            ull p4 = q2.x, p5 = q2.y, p6 = q3.x, p7 = q3.y;
            ull m0 = 0, m1 = 0, m2 = 0, m3 = 0, m4 = 0, m5 = 0, m6 = 0, m7 = 0;
            #pragma unroll 2
            for (int j = 0; j < HID; j++) {
                ulonglong2 wa = w1v[j * 4 + 0], wb = w1v[j * 4 + 1];
                ulonglong2 wc = w1v[j * 4 + 2], wd = w1v[j * 4 + 3];
                ull h = b1d[j];
                h = fma2v(p0, wa.x, h); h = fma2v(p1, wa.y, h);
                h = fma2v(p2, wb.x, h); h = fma2v(p3, wb.y, h);
                h = fma2v(p4, wc.x, h); h = fma2v(p5, wc.y, h);
                h = fma2v(p6, wd.x, h); h = fma2v(p7, wd.y, h);
                float hA, hB; upk2(h, hA, hB);
                hA = fmaxf(hA, 0.f); hB = fmaxf(hB, 0.f);
                h = pk2(hA, hB);
                ulonglong2 ra = w2v[j * 4 + 0], rb = w2v[j * 4 + 1];
                ulonglong2 rc = w2v[j * 4 + 2], rd = w2v[j * 4 + 3];
                m0 = fma2v(h, ra.x, m0); m1 = fma2v(h, ra.y, m1);
                m2 = fma2v(h, rb.x, m2); m3 = fma2v(h, rb.y, m3);
                m4 = fma2v(h, rc.x, m4); m5 = fma2v(h, rc.y, m5);
                m6 = fma2v(h, rd.x, m6); m7 = fma2v(h, rd.y, m7);
            }
            pb0[n] = make_ulonglong2(m0, m1);   // hop-0 outputs (feat0, feat1), {A,B} in lanes
            pb1[n] = make_ulonglong2(m2, m3);
            pb2[n] = make_ulonglong2(m4, m5);
            pb3[n] = make_ulonglong2(m6, m7);
        }
    }
    __syncthreads();

    // layer-2 Horner (in-place addends safe: each ADD[n] owned by its thread):
    GATHER(pb3, pb2, pb2, true); __syncthreads();   // pb2 <- m2 + A m3
    GATHER(pb2, pb1, pb1, true); __syncthreads();   // pb1 <- m1 + A pb2

    // epilogue: out = x + m0 + A pb1 + b2 (x reloaded from gmem via perm)
    float b20 = b2[0], b21 = b2[1];
    float2* ogA = (float2*)out + (size_t)gA * NN;
    float2* ogB = (float2*)out + (size_t)gB * NN;
    for (int n = t; n < NN; n += bs) {
        int b = sptr[n], e = sptr[n + 1];
        ulonglong2 z = pb0[n];
        ull a0 = z.x, a1 = z.y;
        for (int q = b; q < e; q++) {
            int2 ed = se[q];
            float w = __int_as_float(ed.y);
            ull ww = pk2(w, w);
            ulonglong2 v = pb1[ed.x];
            a0 = fma2v(v.x, ww, a0); a1 = fma2v(v.y, ww, a1);
        }
        int node = __ldg(&g_perm[n]);
        float oA0, oB0, oA1, oB1;
        upk2(a0, oA0, oB0); upk2(a1, oA1, oB1);
        float xA0, xA1, xB0, xB1;
        upk2(__ldg(&xgA[node]), xA0, xA1);
        ogA[node] = make_float2(xA0 + oA0 + b20, xA1 + oA1 + b21);
        if (hasB) {
            upk2(__ldg(&xgB[node]), xB0, xB1);
            ogB[node] = make_float2(xB0 + oB0 + b20, xB1 + oB1 + b21);
        }
    }
    #undef GATHER
}

// ---------------- launcher ----------------
extern "C" void kernel_launch(void* const* d_in, const int* in_sizes, int n_in,
                              void* d_out, int out_size) {
    const float* x   = (const float*)d_in[0];
    const int*   row = (const int*)  d_in[1];
    const int*   col = (const int*)  d_in[2];
    const float* ew  = (const float*)d_in[3];
    const float* W1  = (const float*)d_in[4];
    const float* b1  = (const float*)d_in[5];
    const float* W2  = (const float*)d_in[6];
    const float* b2  = (const float*)d_in[7];

    const int E = in_sizes[1];
    const int G = in_sizes[0] / (2 * NN);
    const int nCta = (G + 1) / 2;

    cudaFuncSetAttribute(k_main, cudaFuncAttributeMaxDynamicSharedMemorySize, SMEM_BYTES);

    k_pre<<<1, 1024>>>(row, col, ew, E);
    k_main<<<nCta, TPB, SMEM_BYTES>>>(x, W1, b1, W2, b2, (float*)d_out, G, E);
}

// round 7
// speedup vs baseline: 1.6142x; 1.6142x over previous
#include <cuda_runtime.h>
#include <cuda_bf16.h>

// Fixed-shape problem: N=2000 nodes, F=2, HIDDEN=64, K=3, G=256 graphs, E~7998 edges
#define NN    2000
#define EMAXS 8192          // smem edge capacity (actual E ~7998)
#define HID   64
#define TPB   1024

typedef unsigned long long ull;

// ---------------- f32x2 packed-math helpers ----------------
__device__ __forceinline__ ull pk2(float lo, float hi) {
    ull r; asm("mov.b64 %0,{%1,%2};" : "=l"(r) : "f"(lo), "f"(hi)); return r;
}
__device__ __forceinline__ void upk2(ull v, float& lo, float& hi) {
    asm("mov.b64 {%0,%1}, %2;" : "=f"(lo), "=f"(hi) : "l"(v));
}
__device__ __forceinline__ ull fma2v(ull a, ull b, ull c) {
    ull d; asm("fma.rn.f32x2 %0, %1, %2, %3;" : "=l"(d) : "l"(a), "l"(b), "l"(c)); return d;
}

// ---------------- device-global scratch ----------------
__device__ int  g_ptr[NN + 1];
__device__ int  g_perm[NN];
__device__ int2 g_edge[EMAXS];   // .x = src slot, .y = bits of gcn_norm weight

// ---------------- fused prepass: smem atomics + degree counting-sort ----------------
__global__ __launch_bounds__(1024)
void k_pre(const int* __restrict__ row, const int* __restrict__ col,
           const float* __restrict__ ew, int E) {
    __shared__ float sdeg[NN];
    __shared__ int   scnt[NN];
    __shared__ int   sinv[NN];
    __shared__ int   scur[NN];
    __shared__ int   hist[64];
    __shared__ int   hoff[64];
    __shared__ int   warpsum[32];
    const int t = threadIdx.x;

    for (int i = t; i < NN; i += 1024) { sdeg[i] = 0.f; scnt[i] = 0; }
    if (t < 64) hist[t] = 0;
    __syncthreads();

    for (int e = t; e < E; e += 1024) {
        int c = col[e];
        atomicAdd(&sdeg[c], ew[e]);
        atomicAdd(&scnt[c], 1);
    }
    __syncthreads();

    for (int n = t; n < NN; n += 1024) {
        int d = scnt[n]; if (d > 63) d = 63;
        atomicAdd(&hist[d], 1);
    }
    __syncthreads();
    if (t == 0) {
        int run = 0;
        for (int d = 0; d < 64; d++) { hoff[d] = run; run += hist[d]; }
    }
    __syncthreads();

    for (int n = t; n < NN; n += 1024) {
        int d = scnt[n]; int dc = (d > 63) ? 63 : d;
        int slot = atomicAdd(&hoff[dc], 1);
        sinv[n] = slot;
        g_perm[slot] = n;
        scur[slot] = d;
    }
    __syncthreads();

    {   // exclusive scan of slot-degrees -> g_ptr / cursors
        int i0 = 2 * t, i1 = 2 * t + 1;
        int a0 = (i0 < NN) ? scur[i0] : 0;
        int a1 = (i1 < NN) ? scur[i1] : 0;
        int tot = a0 + a1;
        int lane = t & 31, wid = t >> 5;
        int v = tot;
        #pragma unroll
        for (int o = 1; o < 32; o <<= 1) {
            int u = __shfl_up_sync(0xFFFFFFFFu, v, o);
            if (lane >= o) v += u;
        }
        if (lane == 31) warpsum[wid] = v;
        __syncthreads();
        if (wid == 0) {
            int w = warpsum[lane];
            #pragma unroll
            for (int o = 1; o < 32; o <<= 1) {
                int u = __shfl_up_sync(0xFFFFFFFFu, w, o);
                if (lane >= o) w += u;
            }
            warpsum[lane] = w;
        }
        __syncthreads();
        int base = v - tot + (wid ? warpsum[wid - 1] : 0);
        if (i0 < NN) { scur[i0] = base;      g_ptr[i0] = base; }
        if (i1 < NN) { scur[i1] = base + a0; g_ptr[i1] = base + a0; }
        if (t == 0)  g_ptr[NN] = E;
    }
    __syncthreads();

    for (int e = t; e < E; e += 1024) {
        int r = row[e], c = col[e];
        float dr = sdeg[r], dc = sdeg[c];
        float ir = (dr > 0.f) ? rsqrtf(dr) : 0.f;
        float ic = (dc > 0.f) ? rsqrtf(dc) : 0.f;
        float nrm = ir * ew[e] * ic;
        int p = atomicAdd(&scur[sinv[c]], 1);
        g_edge[p] = make_int2(sinv[r], __float_as_int(nrm));
    }
}

// ---------------- main fused kernel: one CTA per TWO graphs ----------------
// Node buffers: ulonglong2 per node = ( pk2(feat0_A, feat0_B), pk2(feat1_A, feat1_B) )
#define SMEM_BYTES (4 * NN * 16 + EMAXS * 8 + 4096 + 4096 + 512 + (NN + 1) * 4)

__global__ __launch_bounds__(TPB, 1)
void k_main(const float* __restrict__ x,
            const float* __restrict__ W1, const float* __restrict__ b1,
            const float* __restrict__ W2, const float* __restrict__ b2,
            float* __restrict__ out, int G, int E) {
    extern __shared__ float sm[];
    ulonglong2* pb0 = (ulonglong2*)sm;
    ulonglong2* pb1 = pb0 + NN;
    ulonglong2* pb2 = pb1 + NN;
    ulonglong2* pb3 = pb2 + NN;
    int2* se  = (int2*)(pb3 + NN);         // staged edges
    ull*  w1d = (ull*)(se + EMAXS);        // [64 j][8 i]  pk2(W1cat[i][j], dup)
    ull*  w2d = w1d + 512;                 // [64 j][8 c]  pk2(W2cat[j][c], dup)
    ull*  b1d = w2d + 512;                 // [64] pk2(b1[j], dup)
    int*  sptr = (int*)(b1d + 64);

    const int t  = threadIdx.x;
    const int bs = blockDim.x;
    const int gA = 2 * blockIdx.x;
    int gB = gA + 1; bool hasB = (gB < G); if (!hasB) gB = gA;

    // stage duplicated weights
    for (int i = t; i < 512; i += bs) {
        int j = i >> 3, c = i & 7;
        float a = W1[c * HID + j];                             // W1cat[c][j]
        w1d[i] = pk2(a, a);
        float v = W2[(c >> 1) * (HID * 2) + j * 2 + (c & 1)];  // W2cat[j][c]
        w2d[i] = pk2(v, v);
    }
    for (int i = t; i < HID; i += bs) { float v = b1[i]; b1d[i] = pk2(v, v); }
    for (int i = t; i < NN + 1; i += bs) sptr[i] = g_ptr[i];
    for (int i = t; i < E; i += bs) se[i] = g_edge[i];

    // stage x into slot space with {A,B}-in-lanes transpose -> pb0
    const ull* xgA = (const ull*)(x + (size_t)gA * 2 * NN);
    const ull* xgB = (const ull*)(x + (size_t)gB * 2 * NN);
    for (int s = t; s < NN; s += bs) {
        int node = __ldg(&g_perm[s]);
        float a0, a1, c0, c1;
        upk2(__ldg(&xgA[node]), a0, a1);
        upk2(__ldg(&xgB[node]), c0, c1);
        pb0[s] = make_ulonglong2(pk2(a0, c0), pk2(a1, c1));
    }
    __syncthreads();

    // ---- single-slot gather from smem edges ----
    #define GATHER(PIN, POUT, ADD, USE_ADD)                                    \
    _Pragma("unroll 1")                                                        \
    for (int n = t; n < NN; n += bs) {                                         \
        int b = sptr[n], e = sptr[n + 1];                                      \
        ull a0 = 0, a1 = 0;                                                    \
        if (USE_ADD) { ulonglong2 z = ADD[n]; a0 = z.x; a1 = z.y; }            \
        for (int q = b; q < e; q++) {                                          \
            int2 ed = se[q];                                                   \
            float w = __int_as_float(ed.y);                                    \
            ull ww = pk2(w, w);                                                \
            ulonglong2 v = PIN[ed.x];                                          \
            a0 = fma2v(v.x, ww, a0); a1 = fma2v(v.y, ww, a1);                  \
        }                                                                      \
        POUT[n] = make_ulonglong2(a0, a1);                                     \
    }

    // layer-1 hops
    GATHER(pb0, pb1, pb0, false); __syncthreads();
    GATHER(pb1, pb2, pb0, false); __syncthreads();
    GATHER(pb2, pb3, pb0, false); __syncthreads();

    // ---- dense sandwich: [8] -> 64 (relu) -> [8], spill-free (≈48 live regs) ----
    {
        const ulonglong2* w1v = (const ulonglong2*)w1d;   // 4 per j
        const ulonglong2* w2v = (const ulonglong2*)w2d;   // 4 per j
        #pragma unroll 1
        for (int n = t; n < NN; n += bs) {
            ulonglong2 q0 = pb0[n], q1 = pb1[n], q2 = pb2[n], q3 = pb3[n];
            ull p0 = q0.x, p1 = q0.y, p2 = q1.x, p3 = q1.y;
            ull p4 = q2.x, p5 = q2.y, p6 = q3.x, p7 = q3.y;
            ull m0 = 0, m1 = 0, m2 = 0, m3 = 0, m4 = 0, m5 = 0, m6 = 0, m7 = 0;
            #pragma unroll 1
            for (int j = 0; j < HID; j++) {
                ull h = b1d[j];
                ulonglong2 w;
                w = w1v[j * 4 + 0]; h = fma2v(p0, w.x, h); h = fma2v(p1, w.y, h);
                w = w1v[j * 4 + 1]; h = fma2v(p2, w.x, h); h = fma2v(p3, w.y, h);
                w = w1v[j * 4 + 2]; h = fma2v(p4, w.x, h); h = fma2v(p5, w.y, h);
                w = w1v[j * 4 + 3]; h = fma2v(p6, w.x, h); h = fma2v(p7, w.y, h);
                float hA, hB; upk2(h, hA, hB);
                hA = fmaxf(hA, 0.f); hB = fmaxf(hB, 0.f);
                h = pk2(hA, hB);
                w = w2v[j * 4 + 0]; m0 = fma2v(h, w.x, m0); m1 = fma2v(h, w.y, m1);
                w = w2v[j * 4 + 1]; m2 = fma2v(h, w.x, m2); m3 = fma2v(h, w.y, m3);
                w = w2v[j * 4 + 2]; m4 = fma2v(h, w.x, m4); m5 = fma2v(h, w.y, m5);
                w = w2v[j * 4 + 3]; m6 = fma2v(h, w.x, m6); m7 = fma2v(h, w.y, m7);
            }
            pb0[n] = make_ulonglong2(m0, m1);   // hop-0 outputs (feat0, feat1)
            pb1[n] = make_ulonglong2(m2, m3);
            pb2[n] = make_ulonglong2(m4, m5);
            pb3[n] = make_ulonglong2(m6, m7);
        }
    }
    __syncthreads();

    // layer-2 Horner (in-place addends safe: each ADD[n] owned by its thread):
    GATHER(pb3, pb2, pb2, true); __syncthreads();   // pb2 <- m2 + A m3
    GATHER(pb2, pb1, pb1, true); __syncthreads();   // pb1 <- m1 + A pb2

    // epilogue: out = x + m0 + A pb1 + b2 (x reloaded from gmem via perm)
    float b20 = b2[0], b21 = b2[1];
    float2* ogA = (float2*)out + (size_t)gA * NN;
    float2* ogB = (float2*)out + (size_t)gB * NN;
    #pragma unroll 1
    for (int n = t; n < NN; n += bs) {
        int b = sptr[n], e = sptr[n + 1];
        ulonglong2 z = pb0[n];
        ull a0 = z.x, a1 = z.y;
        for (int q = b; q < e; q++) {
            int2 ed = se[q];
            float w = __int_as_float(ed.y);
            ull ww = pk2(w, w);
            ulonglong2 v = pb1[ed.x];
            a0 = fma2v(v.x, ww, a0); a1 = fma2v(v.y, ww, a1);
        }
        int node = __ldg(&g_perm[n]);
        float oA0, oB0, oA1, oB1;
        upk2(a0, oA0, oB0); upk2(a1, oA1, oB1);
        float xA0, xA1, xB0, xB1;
        upk2(__ldg(&xgA[node]), xA0, xA1);
        ogA[node] = make_float2(xA0 + oA0 + b20, xA1 + oA1 + b21);
        if (hasB) {
            upk2(__ldg(&xgB[node]), xB0, xB1);
            ogB[node] = make_float2(xB0 + oB0 + b20, xB1 + oB1 + b21);
        }
    }
    #undef GATHER
}

// ---------------- launcher ----------------
extern "C" void kernel_launch(void* const* d_in, const int* in_sizes, int n_in,
                              void* d_out, int out_size) {
    const float* x   = (const float*)d_in[0];
    const int*   row = (const int*)  d_in[1];
    const int*   col = (const int*)  d_in[2];
    const float* ew  = (const float*)d_in[3];
    const float* W1  = (const float*)d_in[4];
    const float* b1  = (const float*)d_in[5];
    const float* W2  = (const float*)d_in[6];
    const float* b2  = (const float*)d_in[7];

    const int E = in_sizes[1];
    const int G = in_sizes[0] / (2 * NN);
    const int nCta = (G + 1) / 2;

    cudaFuncSetAttribute(k_main, cudaFuncAttributeMaxDynamicSharedMemorySize, SMEM_BYTES);

    k_pre<<<1, 1024>>>(row, col, ew, E);
    k_main<<<nCta, TPB, SMEM_BYTES>>>(x, W1, b1, W2, b2, (float*)d_out, G, E);
}